// round 5
// baseline (speedup 1.0000x reference)
#include <cuda_runtime.h>
#include <cstdint>

#define MAX_NODES 100000
#define MAX_EDGES 1600000
#define F1 32
#define F2 16
#define F3 2
#define SEG 256
#define MAX_SEGN 512
#define TPB 256

// Scratch (device globals; no allocation allowed)
__device__ __align__(256) float g_y1[MAX_NODES * F1];
__device__ __align__(256) float g_h1[MAX_NODES * F1];
__device__ __align__(256) float g_y2[MAX_NODES * F2];
__device__ __align__(256) float g_h2[MAX_NODES * F2];
__device__ __align__(256) float g_y3[MAX_NODES * F3];
__device__ __align__(256) float g_h3[MAX_NODES * F3];

__device__ __align__(256) int g_cnt[MAX_NODES];      // in-degree histogram
__device__ __align__(256) int g_cur[MAX_NODES];      // fill cursor
__device__ __align__(256) int g_row[MAX_NODES + 1];  // CSR row offsets
__device__ __align__(256) int g_bsum[MAX_SEGN];      // scan spine
__device__ __align__(256) int g_srcs[MAX_EDGES];     // CSR columns (src ids)

// Grid barrier (count resets each barrier; gen monotonic across replays)
__device__ unsigned g_bar_cnt = 0;
__device__ volatile unsigned g_bar_gen = 0;

__device__ __forceinline__ void grid_sync() {
    __syncthreads();
    if (threadIdx.x == 0) {
        __threadfence();                           // release
        unsigned gen = g_bar_gen;
        unsigned arrived = atomicAdd(&g_bar_cnt, 1u);
        if (arrived == gridDim.x - 1) {
            g_bar_cnt = 0;
            __threadfence();
            g_bar_gen = gen + 1;                   // publish
        } else {
            while (g_bar_gen == gen) { }           // spin
            __threadfence();                       // acquire
        }
    }
    __syncthreads();
}

// ---------------------------------------------------------------------------
// Transform: y = act(x) @ Wrel ; h = act(x) @ Wroot + b.
// Work item = (rel|root, output-chunk of <=16, node). 16 accumulators max
// keeps regs under the 64-reg/4-block occupancy budget. Weights in SMEM,
// read as float4 broadcasts.
// ---------------------------------------------------------------------------
template <int FIN, int FOUT, bool RELU>
__device__ __forceinline__ void transform_phase(
    const float* __restrict__ x,
    const float* __restrict__ Wrel, const float* __restrict__ Wroot,
    const float* __restrict__ b,
    float* __restrict__ y, float* __restrict__ h,
    int n, float* s_w, int gtid, int T) {

    constexpr int OCH = (FOUT >= 16) ? 16 : FOUT;
    constexpr int NCH = FOUT / OCH;

    for (int i = threadIdx.x; i < FIN * FOUT; i += blockDim.x) {
        s_w[i] = Wrel[i];
        s_w[FIN * FOUT + i] = Wroot[i];
    }
    for (int i = threadIdx.x; i < FOUT; i += blockDim.x)
        s_w[2 * FIN * FOUT + i] = b[i];
    __syncthreads();
    const float* s_b = s_w + 2 * FIN * FOUT;

    const int total = 2 * NCH * n;
    for (int it = gtid; it < total; it += T) {
        const int sel = it / n;
        const int node = it - sel * n;
        const bool isRel = sel < NCH;
        const int chunk = isRel ? sel : sel - NCH;
        const float* W = (isRel ? s_w : s_w + FIN * FOUT) + chunk * OCH;

        float acc[OCH];
#pragma unroll
        for (int j = 0; j < OCH; j++) acc[j] = isRel ? 0.f : s_b[chunk * OCH + j];

        const float4* xr = reinterpret_cast<const float4*>(x + (size_t)node * FIN);
#pragma unroll
        for (int kk = 0; kk < FIN / 4; kk++) {
            float4 xv = __ldg(xr + kk);
            float xs[4] = {xv.x, xv.y, xv.z, xv.w};
#pragma unroll
            for (int q = 0; q < 4; q++) {
                float v = RELU ? fmaxf(xs[q], 0.f) : xs[q];
                const float* Wr = W + (kk * 4 + q) * FOUT;
                if constexpr (OCH >= 4) {
#pragma unroll
                    for (int j4 = 0; j4 < OCH / 4; j4++) {
                        float4 wv = reinterpret_cast<const float4*>(Wr)[j4];
                        acc[j4 * 4 + 0] = fmaf(v, wv.x, acc[j4 * 4 + 0]);
                        acc[j4 * 4 + 1] = fmaf(v, wv.y, acc[j4 * 4 + 1]);
                        acc[j4 * 4 + 2] = fmaf(v, wv.z, acc[j4 * 4 + 2]);
                        acc[j4 * 4 + 3] = fmaf(v, wv.w, acc[j4 * 4 + 3]);
                    }
                } else {
#pragma unroll
                    for (int j = 0; j < OCH; j++) acc[j] = fmaf(v, Wr[j], acc[j]);
                }
            }
        }

        float* o = (isRel ? y : h) + (size_t)node * FOUT + chunk * OCH;
        if constexpr (OCH >= 4) {
#pragma unroll
            for (int j4 = 0; j4 < OCH / 4; j4++)
                reinterpret_cast<float4*>(o)[j4] =
                    make_float4(acc[j4 * 4], acc[j4 * 4 + 1], acc[j4 * 4 + 2], acc[j4 * 4 + 3]);
        } else {
            *reinterpret_cast<float2*>(o) = make_float2(acc[0], acc[1]);
        }
    }
}

// ---------------------------------------------------------------------------
// Pull aggregation: one warp per node. Prefetch up to 32 src ids per chunk,
// shfl-broadcast ids so gathers are independent (MLP ~= STEPS). CH lanes
// cover one contiguous row (float4 each); RPI rows in flight per step.
// h[node] += sum_{src in N(node)} y[src]   (h already holds root + bias).
// ---------------------------------------------------------------------------
template <int F>
__device__ __forceinline__ void agg_phase(
    const int* __restrict__ row, const int* __restrict__ srcs,
    const float* __restrict__ y, float* __restrict__ h,
    int n, int gtid, int T) {
    constexpr int CH = F / 4;
    constexpr int RPI = 32 / CH;
    constexpr int STEPS = 32 / RPI;
    const int lane = threadIdx.x & 31;
    const int sub = lane / CH;
    const int c = lane % CH;
    const int nw = T >> 5;

    for (int w = gtid >> 5; w < n; w += nw) {
        const int start = row[w];
        const int end = row[w + 1];
        float4 acc = make_float4(0.f, 0.f, 0.f, 0.f);

        for (int base = start; base < end; base += 32) {
            const int cnt = min(32, end - base);
            int sj = 0;
            if (lane < cnt) sj = srcs[base + lane];
#pragma unroll
            for (int s = 0; s < STEPS; s++) {
                const int idx = s * RPI + sub;
                const int src = __shfl_sync(0xffffffffu, sj, idx);
                if (idx < cnt) {
                    float4 v = __ldg(reinterpret_cast<const float4*>(y + (size_t)src * F + c * 4));
                    acc.x += v.x; acc.y += v.y; acc.z += v.z; acc.w += v.w;
                }
            }
        }
#pragma unroll
        for (int off = 16; off >= CH; off >>= 1) {
            acc.x += __shfl_down_sync(0xffffffffu, acc.x, off);
            acc.y += __shfl_down_sync(0xffffffffu, acc.y, off);
            acc.z += __shfl_down_sync(0xffffffffu, acc.z, off);
            acc.w += __shfl_down_sync(0xffffffffu, acc.w, off);
        }
        if (lane < CH) {
            float4* hp = reinterpret_cast<float4*>(h + (size_t)w * F) + lane;
            float4 r = *hp;
            r.x += acc.x; r.y += acc.y; r.z += acc.z; r.w += acc.w;
            *hp = r;
        }
    }
}

// Layer-3 aggregation (F=2) fused with 2-class softmax.
__device__ __forceinline__ void agg3_softmax_phase(
    const int* __restrict__ row, const int* __restrict__ srcs,
    const float* __restrict__ y, const float* __restrict__ h,
    float* __restrict__ out, int n, int gtid, int T) {
    const int lane = threadIdx.x & 31;
    const int nw = T >> 5;
    for (int w = gtid >> 5; w < n; w += nw) {
        const int start = row[w];
        const int end = row[w + 1];
        float ax = 0.f, ay = 0.f;
        for (int i = start + lane; i < end; i += 32) {
            int src = srcs[i];
            float2 v = __ldg(reinterpret_cast<const float2*>(y + 2 * (size_t)src));
            ax += v.x; ay += v.y;
        }
#pragma unroll
        for (int off = 16; off > 0; off >>= 1) {
            ax += __shfl_down_sync(0xffffffffu, ax, off);
            ay += __shfl_down_sync(0xffffffffu, ay, off);
        }
        if (lane == 0) {
            float2 r = *reinterpret_cast<const float2*>(h + 2 * (size_t)w);
            float vx = r.x + ax, vy = r.y + ay;
            float m = fmaxf(vx, vy);
            float ea = __expf(vx - m);
            float eb = __expf(vy - m);
            float inv = 1.0f / (ea + eb);
            reinterpret_cast<float2*>(out)[w] = make_float2(ea * inv, eb * inv);
        }
    }
}

// ---------------------------------------------------------------------------
// One persistent kernel: CSR build + 3 layers + softmax, 10 grid barriers.
// ---------------------------------------------------------------------------
__global__ void __launch_bounds__(TPB, 4)
gnn_persistent(const float* __restrict__ z, const int* __restrict__ ei,
               const float* __restrict__ Wrel1, const float* __restrict__ Wroot1, const float* __restrict__ b1,
               const float* __restrict__ Wrel2, const float* __restrict__ Wroot2, const float* __restrict__ b2,
               const float* __restrict__ Wrel3, const float* __restrict__ Wroot3, const float* __restrict__ b3,
               float* __restrict__ out, int n, int e, int nseg) {
    __shared__ __align__(16) float s_w[2 * 64 * F1 + F1];   // 16.5 KB; aliased by scans
    const int T = gridDim.x * blockDim.x;
    const int gtid = blockIdx.x * blockDim.x + threadIdx.x;

    // A: zero histogram + layer-1 transform (independent work, one phase)
    for (int i = gtid; i < n; i += T) g_cnt[i] = 0;
    transform_phase<64, F1, false>(z, Wrel1, Wroot1, b1, g_y1, g_h1, n, s_w, gtid, T);
    grid_sync();

    // B: in-degree histogram
    for (int t = gtid; t < e; t += T)
        atomicAdd(&g_cnt[__ldg(ei + e + t)], 1);
    grid_sync();

    // C: per-segment partial sums
    {
        int* s_i = reinterpret_cast<int*>(s_w);
        for (int seg = blockIdx.x; seg < nseg; seg += gridDim.x) {
            int i = seg * SEG + threadIdx.x;
            int v = (i < n) ? g_cnt[i] : 0;
            s_i[threadIdx.x] = v;
            __syncthreads();
            for (int off = TPB / 2; off > 0; off >>= 1) {
                if (threadIdx.x < off) s_i[threadIdx.x] += s_i[threadIdx.x + off];
                __syncthreads();
            }
            if (threadIdx.x == 0) g_bsum[seg] = s_i[0];
            __syncthreads();
        }
    }
    grid_sync();

    // D: spine exclusive scan (warp 0 of block 0; nseg <= 512, 16 elems/lane)
    if (blockIdx.x == 0 && threadIdx.x < 32) {
        const int lane = threadIdx.x;
        int vals[16];
        int lsum = 0;
#pragma unroll
        for (int q = 0; q < 16; q++) {
            int idx = lane * 16 + q;
            vals[q] = (idx < nseg) ? g_bsum[idx] : 0;
            lsum += vals[q];
        }
        int inc = lsum;
#pragma unroll
        for (int off = 1; off < 32; off <<= 1) {
            int o = __shfl_up_sync(0xffffffffu, inc, off);
            if (lane >= off) inc += o;
        }
        int run = inc - lsum;  // exclusive prefix of this lane's group
#pragma unroll
        for (int q = 0; q < 16; q++) {
            int idx = lane * 16 + q;
            if (idx < nseg) g_bsum[idx] = run;
            run += vals[q];
        }
    }
    grid_sync();

    // E: final per-segment exclusive scan -> row offsets + fill cursors
    {
        int* s_i = reinterpret_cast<int*>(s_w);
        for (int seg = blockIdx.x; seg < nseg; seg += gridDim.x) {
            int i = seg * SEG + threadIdx.x;
            int v = (i < n) ? g_cnt[i] : 0;
            s_i[threadIdx.x] = v;
            __syncthreads();
            for (int off = 1; off < TPB; off <<= 1) {
                int x = (threadIdx.x >= off) ? s_i[threadIdx.x - off] : 0;
                __syncthreads();
                s_i[threadIdx.x] += x;
                __syncthreads();
            }
            if (i < n) {
                int val = g_bsum[seg] + s_i[threadIdx.x] - v;  // exclusive
                g_row[i] = val;
                g_cur[i] = val;
            }
            __syncthreads();
        }
        if (gtid == 0) g_row[n] = e;
    }
    grid_sync();

    // F: bucket fill (CSR columns)
    for (int t = gtid; t < e; t += T) {
        int dst = __ldg(ei + e + t);
        int pos = atomicAdd(&g_cur[dst], 1);
        g_srcs[pos] = __ldg(ei + t);
    }
    grid_sync();

    // Layer 1 aggregation
    agg_phase<F1>(g_row, g_srcs, g_y1, g_h1, n, gtid, T);
    grid_sync();
    // Layer 2
    transform_phase<F1, F2, true>(g_h1, Wrel2, Wroot2, b2, g_y2, g_h2, n, s_w, gtid, T);
    grid_sync();
    agg_phase<F2>(g_row, g_srcs, g_y2, g_h2, n, gtid, T);
    grid_sync();
    // Layer 3 + fused softmax
    transform_phase<F2, F3, true>(g_h2, Wrel3, Wroot3, b3, g_y3, g_h3, n, s_w, gtid, T);
    grid_sync();
    agg3_softmax_phase(g_row, g_srcs, g_y3, g_h3, out, n, gtid, T);
}

extern "C" void kernel_launch(void* const* d_in, const int* in_sizes, int n_in,
                              void* d_out, int out_size) {
    const float* z      = (const float*)d_in[0];
    const int*   ei     = (const int*)d_in[1];   // int32 (JAX x64 disabled)
    const float* Wrel1  = (const float*)d_in[2];
    const float* Wroot1 = (const float*)d_in[3];
    const float* b1     = (const float*)d_in[4];
    const float* Wrel2  = (const float*)d_in[5];
    const float* Wroot2 = (const float*)d_in[6];
    const float* b2     = (const float*)d_in[7];
    const float* Wrel3  = (const float*)d_in[8];
    const float* Wroot3 = (const float*)d_in[9];
    const float* b3     = (const float*)d_in[10];

    const int n = in_sizes[0] / 64;   // 100000
    const int e = in_sizes[1] / 2;    // 1600000
    const int nseg = (n + SEG - 1) / SEG;

    int dev = 0, sm = 0, occ = 0;
    cudaGetDevice(&dev);
    cudaDeviceGetAttribute(&sm, cudaDevAttrMultiProcessorCount, dev);
    cudaOccupancyMaxActiveBlocksPerMultiprocessor(&occ, gnn_persistent, TPB, 0);
    if (occ < 1) occ = 1;
    const int blocks = sm * occ;

    gnn_persistent<<<blocks, TPB>>>(z, ei,
                                    Wrel1, Wroot1, b1,
                                    Wrel2, Wroot2, b2,
                                    Wrel3, Wroot3, b3,
                                    (float*)d_out, n, e, nseg);
}